// round 2
// baseline (speedup 1.0000x reference)
#include <cuda_runtime.h>

typedef unsigned long long u64;

#define HID 128
#define NA  1024
#define NR  1024

// Scratch: PA (bs1 folded in) and PR, row-major [row][h]
__device__ float g_PA[NA * HID];
__device__ float g_PR[NR * HID];

// ---------------- packed f32x2 helpers (sm_103a FADD2/FFMA2) ----------------
__device__ __forceinline__ u64 dup2(float v) {
    u64 d; asm("mov.b64 %0,{%1,%1};" : "=l"(d) : "f"(v)); return d;
}
__device__ __forceinline__ u64 pack2(float lo, float hi) {
    u64 d; asm("mov.b64 %0,{%1,%2};" : "=l"(d) : "f"(lo), "f"(hi)); return d;
}
__device__ __forceinline__ float2 unpack2(u64 d) {
    float2 r; asm("mov.b64 {%0,%1},%2;" : "=f"(r.x), "=f"(r.y) : "l"(d)); return r;
}
__device__ __forceinline__ u64 fadd2_(u64 a, u64 b) {
    u64 d; asm("add.rn.f32x2 %0,%1,%2;" : "=l"(d) : "l"(a), "l"(b)); return d;
}
__device__ __forceinline__ u64 ffma2_(u64 a, u64 b, u64 c) {
    u64 d; asm("fma.rn.f32x2 %0,%1,%2,%3;" : "=l"(d) : "l"(a), "l"(b), "l"(c)); return d;
}
__device__ __forceinline__ u64 relu2_(u64 x) {
    u64 d;
    asm("{\n\t.reg .f32 lo,hi;\n\t"
        "mov.b64 {lo,hi},%1;\n\t"
        "max.f32 lo,lo,0f00000000;\n\t"
        "max.f32 hi,hi,0f00000000;\n\t"
        "mov.b64 %0,{lo,hi};\n\t}"
        : "=l"(d) : "l"(x));
    return d;
}
// acc += relu(a2 + r2) * w2   (packed over 2 lanes)
__device__ __forceinline__ u64 addrelufma(u64 acc, u64 a2, u64 r2, u64 w2) {
    asm("{\n\t.reg .b64 t;\n\t.reg .f32 lo,hi;\n\t"
        "add.rn.f32x2 t,%1,%2;\n\t"
        "mov.b64 {lo,hi},t;\n\t"
        "max.f32 lo,lo,0f00000000;\n\t"
        "max.f32 hi,hi,0f00000000;\n\t"
        "mov.b64 t,{lo,hi};\n\t"
        "fma.rn.f32x2 %0,t,%3,%0;\n\t}"
        : "+l"(acc) : "l"(a2), "l"(r2), "l"(w2));
    return acc;
}

// ---------------------------------------------------------------------------
// Kernel 1: fused MLP chain, 8 rows per block (weights amortized 8x).
// 256 blocks (128 agent, 128 region), 128 threads; thread j = column j.
// Activations staged transposed [k][row-pair] as packed f32x2.
// ---------------------------------------------------------------------------
__global__ __launch_bounds__(128) void embed_kernel(
    const float* __restrict__ xa,  const float* __restrict__ xr,
    const float* __restrict__ Wa1, const float* __restrict__ ba1,
    const float* __restrict__ Wa2, const float* __restrict__ ba2,
    const float* __restrict__ Wr1, const float* __restrict__ br1,
    const float* __restrict__ Wr2, const float* __restrict__ br2,
    const float* __restrict__ Ws1, const float* __restrict__ bs1)
{
    const int ROWS = 8;
    int blk = blockIdx.x;
    bool agent = blk < 128;
    int rbase = (agent ? blk : blk - 128) * ROWS;
    int idim = agent ? 24 : 20;
    const float* x  = agent ? (xa + rbase * 24) : (xr + rbase * 20);
    const float* W1 = agent ? Wa1 : Wr1;
    const float* b1 = agent ? ba1 : br1;
    const float* W2 = agent ? Wa2 : Wr2;
    const float* b2 = agent ? ba2 : br2;
    const float* Ws = agent ? Ws1 : (Ws1 + HID * HID);
    float* outp = agent ? g_PA : g_PR;

    __shared__ __align__(16) float xs[ROWS * 24];
    __shared__ __align__(16) u64 hT[HID][4];   // [k][row-pair], packed f32x2

    int j = threadIdx.x;

    for (int i = j; i < ROWS * idim; i += 128)
        xs[(i / idim) * 24 + (i % idim)] = x[i];
    __syncthreads();

    // Layer 1 (scalar; only idim k's)
    float acc[ROWS];
    #pragma unroll
    for (int r = 0; r < ROWS; ++r) acc[r] = b1[j];
    for (int k = 0; k < idim; ++k) {
        float w = W1[k * HID + j];
        #pragma unroll
        for (int r = 0; r < ROWS; ++r)
            acc[r] = fmaf(xs[r * 24 + k], w, acc[r]);
    }
    #pragma unroll
    for (int p = 0; p < 4; ++p)
        hT[j][p] = pack2(fmaxf(acc[2 * p], 0.f), fmaxf(acc[2 * p + 1], 0.f));
    __syncthreads();

    // Layer 2 (packed row-pairs)
    u64 acc2[4];
    #pragma unroll
    for (int p = 0; p < 4; ++p) acc2[p] = 0ull;
    #pragma unroll 4
    for (int k = 0; k < HID; ++k) {
        u64 w2 = dup2(W2[k * HID + j]);
        ulonglong2 p01 = *(const ulonglong2*)&hT[k][0];
        ulonglong2 p23 = *(const ulonglong2*)&hT[k][2];
        acc2[0] = ffma2_(p01.x, w2, acc2[0]);
        acc2[1] = ffma2_(p01.y, w2, acc2[1]);
        acc2[2] = ffma2_(p23.x, w2, acc2[2]);
        acc2[3] = ffma2_(p23.y, w2, acc2[3]);
    }
    __syncthreads();
    {
        u64 b2d = dup2(b2[j]);
        #pragma unroll
        for (int p = 0; p < 4; ++p)
            hT[j][p] = relu2_(fadd2_(acc2[p], b2d));
    }
    __syncthreads();

    // Score projection
    #pragma unroll
    for (int p = 0; p < 4; ++p) acc2[p] = 0ull;
    #pragma unroll 4
    for (int k = 0; k < HID; ++k) {
        u64 w2 = dup2(Ws[k * HID + j]);
        ulonglong2 p01 = *(const ulonglong2*)&hT[k][0];
        ulonglong2 p23 = *(const ulonglong2*)&hT[k][2];
        acc2[0] = ffma2_(p01.x, w2, acc2[0]);
        acc2[1] = ffma2_(p01.y, w2, acc2[1]);
        acc2[2] = ffma2_(p23.x, w2, acc2[2]);
        acc2[3] = ffma2_(p23.y, w2, acc2[3]);
    }
    u64 bsd = agent ? dup2(bs1[j]) : 0ull;
    #pragma unroll
    for (int p = 0; p < 4; ++p) {
        u64 v = agent ? fadd2_(acc2[p], bsd) : acc2[p];
        float2 f = unpack2(v);
        outp[(rbase + 2 * p) * HID + j]     = f.x;
        outp[(rbase + 2 * p + 1) * HID + j] = f.y;
    }
}

// ---------------------------------------------------------------------------
// Kernel 2: pairwise scores with packed f32x2 math.
// Block tile: 64 agents x 32 regions, 128 threads, 4a x 4r per thread
// (regions packed in pairs). Agent tile stored DUPLICATED ((v,v) per entry)
// so LDS.128 directly yields broadcast-packed operands. h in 2 chunks of 64.
// ---------------------------------------------------------------------------
__global__ __launch_bounds__(128, 4) void pair_kernel(
    const float* __restrict__ Ws2, const float* __restrict__ bs2,
    float* __restrict__ out)
{
    __shared__ __align__(16) u64   As2[64 * 64];  // [h][a] duplicated, 32KB
    __shared__ __align__(16) float Rs[64 * 32];   // [h][r], 8KB
    __shared__ __align__(16) u64   ws2[HID];      // duplicated w, 1KB

    int t  = threadIdx.x;
    int tx = t & 7;          // region group: r = 4*tx .. +3  (2 pairs)
    int ty = t >> 3;         // agent group:  a = 4*ty .. +3
    int a0 = blockIdx.y * 64;
    int r0 = blockIdx.x * 32;

    ws2[t] = dup2(Ws2[t]);

    u64 acc[4][2];
    #pragma unroll
    for (int i = 0; i < 4; ++i) { acc[i][0] = 0ull; acc[i][1] = 0ull; }

    int aa  = t & 63, hqa = t >> 6;   // A-fill mapping
    int rr  = t & 31, hqr = t >> 5;   // R-fill mapping

    for (int chunk = 0; chunk < 2; ++chunk) {
        int hb = chunk * 64;
        __syncthreads();   // previous chunk's reads done (and ws2 on chunk 0)

        // Fill A tile transposed+duplicated: As2[h_local][a] = (v,v)
        #pragma unroll
        for (int it = 0; it < 8; ++it) {
            int hq = hqa + 2 * it;
            float4 v = *(const float4*)&g_PA[(size_t)(a0 + aa) * HID + hb + 4 * hq];
            As2[(4 * hq + 0) * 64 + aa] = dup2(v.x);
            As2[(4 * hq + 1) * 64 + aa] = dup2(v.y);
            As2[(4 * hq + 2) * 64 + aa] = dup2(v.z);
            As2[(4 * hq + 3) * 64 + aa] = dup2(v.w);
        }
        // Fill R tile transposed: Rs[h_local][r]
        #pragma unroll
        for (int it = 0; it < 4; ++it) {
            int hq = hqr + 4 * it;
            float4 v = *(const float4*)&g_PR[(size_t)(r0 + rr) * HID + hb + 4 * hq];
            Rs[(4 * hq + 0) * 32 + rr] = v.x;
            Rs[(4 * hq + 1) * 32 + rr] = v.y;
            Rs[(4 * hq + 2) * 32 + rr] = v.z;
            Rs[(4 * hq + 3) * 32 + rr] = v.w;
        }
        __syncthreads();

        #pragma unroll 4
        for (int h = 0; h < 64; ++h) {
            ulonglong2 aA = *(const ulonglong2*)&As2[h * 64 + 4 * ty];     // (a0,a0),(a1,a1)
            ulonglong2 aB = *(const ulonglong2*)&As2[h * 64 + 4 * ty + 2]; // (a2,a2),(a3,a3)
            ulonglong2 rv = *(const ulonglong2*)&Rs[h * 32 + 4 * tx];      // (r0,r1),(r2,r3)
            u64 w2 = ws2[hb + h];
            acc[0][0] = addrelufma(acc[0][0], aA.x, rv.x, w2);
            acc[0][1] = addrelufma(acc[0][1], aA.x, rv.y, w2);
            acc[1][0] = addrelufma(acc[1][0], aA.y, rv.x, w2);
            acc[1][1] = addrelufma(acc[1][1], aA.y, rv.y, w2);
            acc[2][0] = addrelufma(acc[2][0], aB.x, rv.x, w2);
            acc[2][1] = addrelufma(acc[2][1], aB.x, rv.y, w2);
            acc[3][0] = addrelufma(acc[3][0], aB.y, rv.x, w2);
            acc[3][1] = addrelufma(acc[3][1], aB.y, rv.y, w2);
        }
    }

    float b = *bs2;
    #pragma unroll
    for (int i = 0; i < 4; ++i) {
        float2 p0 = unpack2(acc[i][0]);
        float2 p1 = unpack2(acc[i][1]);
        float4 o = make_float4(p0.x + b, p0.y + b, p1.x + b, p1.y + b);
        *(float4*)&out[(size_t)(a0 + 4 * ty + i) * NR + r0 + 4 * tx] = o;
    }
}

// ---------------------------------------------------------------------------
extern "C" void kernel_launch(void* const* d_in, const int* in_sizes, int n_in,
                              void* d_out, int out_size)
{
    const float* xa  = (const float*)d_in[0];
    const float* xr  = (const float*)d_in[1];
    const float* Wa1 = (const float*)d_in[2];
    const float* ba1 = (const float*)d_in[3];
    const float* Wa2 = (const float*)d_in[4];
    const float* ba2 = (const float*)d_in[5];
    const float* Wr1 = (const float*)d_in[6];
    const float* br1 = (const float*)d_in[7];
    const float* Wr2 = (const float*)d_in[8];
    const float* br2 = (const float*)d_in[9];
    const float* Ws1 = (const float*)d_in[10];
    const float* bs1 = (const float*)d_in[11];
    const float* Ws2 = (const float*)d_in[12];
    const float* bs2 = (const float*)d_in[13];
    float* out = (float*)d_out;

    embed_kernel<<<256, 128>>>(xa, xr, Wa1, ba1, Wa2, ba2,
                               Wr1, br1, Wr2, br2, Ws1, bs1);
    pair_kernel<<<dim3(NR / 32, NA / 64), 128>>>(Ws2, bs2, out);
}

// round 3
// speedup vs baseline: 1.4171x; 1.4171x over previous
#include <cuda_runtime.h>

typedef unsigned long long u64;

#define HID 128
#define NA  1024
#define NR  1024

// Scratch: PA (bs1 folded in) and PR, row-major [row][h]
__device__ float g_PA[NA * HID];
__device__ float g_PR[NR * HID];

// ---------------- packed f32x2 helpers (sm_103a FADD2/FFMA2) ----------------
__device__ __forceinline__ u64 dup2(float v) {
    u64 d; asm("mov.b64 %0,{%1,%1};" : "=l"(d) : "f"(v)); return d;
}
__device__ __forceinline__ u64 pack2(float lo, float hi) {
    u64 d; asm("mov.b64 %0,{%1,%2};" : "=l"(d) : "f"(lo), "f"(hi)); return d;
}
__device__ __forceinline__ float2 unpack2(u64 d) {
    float2 r; asm("mov.b64 {%0,%1},%2;" : "=f"(r.x), "=f"(r.y) : "l"(d)); return r;
}
__device__ __forceinline__ u64 fadd2_(u64 a, u64 b) {
    u64 d; asm("add.rn.f32x2 %0,%1,%2;" : "=l"(d) : "l"(a), "l"(b)); return d;
}
__device__ __forceinline__ u64 ffma2_(u64 a, u64 b, u64 c) {
    u64 d; asm("fma.rn.f32x2 %0,%1,%2,%3;" : "=l"(d) : "l"(a), "l"(b), "l"(c)); return d;
}
__device__ __forceinline__ u64 relu2_(u64 x) {
    u64 d;
    asm("{\n\t.reg .f32 lo,hi;\n\t"
        "mov.b64 {lo,hi},%1;\n\t"
        "max.f32 lo,lo,0f00000000;\n\t"
        "max.f32 hi,hi,0f00000000;\n\t"
        "mov.b64 %0,{lo,hi};\n\t}"
        : "=l"(d) : "l"(x));
    return d;
}
// acc += relu(a2 + r2) * w2   (2 h-lanes packed)
__device__ __forceinline__ u64 addrelufma(u64 acc, u64 a2, u64 r2, u64 w2) {
    asm("{\n\t.reg .b64 t;\n\t.reg .f32 lo,hi;\n\t"
        "add.rn.f32x2 t,%1,%2;\n\t"
        "mov.b64 {lo,hi},t;\n\t"
        "max.f32 lo,lo,0f00000000;\n\t"
        "max.f32 hi,hi,0f00000000;\n\t"
        "mov.b64 t,{lo,hi};\n\t"
        "fma.rn.f32x2 %0,t,%3,%0;\n\t}"
        : "+l"(acc) : "l"(a2), "l"(r2), "l"(w2));
    return acc;
}

// ---------------------------------------------------------------------------
// 128x128 MLP layer pass, f32x2 row-pairs, 8-deep register prefetch of the
// weight column. hT is [k][row-pair] (broadcast reads, conflict-free).
// ---------------------------------------------------------------------------
__device__ __forceinline__ void mlp128(const float* __restrict__ Wp, int j, int pb,
                                       const u64 (*__restrict__ hT)[8], u64 acc[4])
{
    acc[0] = acc[1] = acc[2] = acc[3] = 0ull;
    float wA[8], wB[8];
    #pragma unroll
    for (int i = 0; i < 8; ++i) wA[i] = Wp[i * HID + j];
    #pragma unroll 1
    for (int kb = 0; kb < 128; kb += 16) {
        #pragma unroll
        for (int i = 0; i < 8; ++i) wB[i] = Wp[(kb + 8 + i) * HID + j];
        #pragma unroll
        for (int i = 0; i < 8; ++i) {
            int k = kb + i;
            u64 w2 = dup2(wA[i]);
            ulonglong2 x01 = *(const ulonglong2*)&hT[k][pb];
            ulonglong2 x23 = *(const ulonglong2*)&hT[k][pb + 2];
            acc[0] = ffma2_(x01.x, w2, acc[0]);
            acc[1] = ffma2_(x01.y, w2, acc[1]);
            acc[2] = ffma2_(x23.x, w2, acc[2]);
            acc[3] = ffma2_(x23.y, w2, acc[3]);
        }
        #pragma unroll
        for (int i = 0; i < 8; ++i)
            wA[i] = (kb + 16 + i < 128) ? Wp[(kb + 16 + i) * HID + j] : 0.f;
        #pragma unroll
        for (int i = 0; i < 8; ++i) {
            int k = kb + 8 + i;
            u64 w2 = dup2(wB[i]);
            ulonglong2 x01 = *(const ulonglong2*)&hT[k][pb];
            ulonglong2 x23 = *(const ulonglong2*)&hT[k][pb + 2];
            acc[0] = ffma2_(x01.x, w2, acc[0]);
            acc[1] = ffma2_(x01.y, w2, acc[1]);
            acc[2] = ffma2_(x23.x, w2, acc[2]);
            acc[3] = ffma2_(x23.y, w2, acc[3]);
        }
    }
}

// ---------------------------------------------------------------------------
// Kernel 1: fused MLP chain. 128 blocks (64 agent + 64 region) x 256 threads,
// 16 rows per block. j = t&127 (column), half = t>>7 picks 4 of 8 row-pairs.
// ---------------------------------------------------------------------------
__global__ __launch_bounds__(256) void embed_kernel(
    const float* __restrict__ xa,  const float* __restrict__ xr,
    const float* __restrict__ Wa1, const float* __restrict__ ba1,
    const float* __restrict__ Wa2, const float* __restrict__ ba2,
    const float* __restrict__ Wr1, const float* __restrict__ br1,
    const float* __restrict__ Wr2, const float* __restrict__ br2,
    const float* __restrict__ Ws1, const float* __restrict__ bs1)
{
    const int ROWS = 16;
    int blk = blockIdx.x;
    bool agent = blk < 64;
    int rbase = (agent ? blk : blk - 64) * ROWS;
    int idim = agent ? 24 : 20;
    const float* x  = agent ? (xa + rbase * 24) : (xr + rbase * 20);
    const float* W1 = agent ? Wa1 : Wr1;
    const float* b1 = agent ? ba1 : br1;
    const float* W2 = agent ? Wa2 : Wr2;
    const float* b2 = agent ? ba2 : br2;
    const float* Ws = agent ? Ws1 : (Ws1 + HID * HID);
    float* outp = agent ? g_PA : g_PR;

    __shared__ __align__(16) u64 xsp[24][8];   // packed input [k][row-pair]
    __shared__ __align__(16) u64 hT[HID][8];   // packed activ [k][row-pair]

    int t = threadIdx.x;
    int j = t & 127;
    int pb = (t >> 7) * 4;     // row-pair base (0 or 4)

    // Stage packed input rows
    for (int i = t; i < idim * 8; i += 256) {
        int k = i >> 3, p = i & 7;
        xsp[k][p] = pack2(x[(2 * p) * idim + k], x[(2 * p + 1) * idim + k]);
    }
    __syncthreads();

    // Layer 1
    u64 acc[4];
    {
        u64 bp = dup2(b1[j]);
        acc[0] = acc[1] = acc[2] = acc[3] = bp;
        #pragma unroll 4
        for (int k = 0; k < idim; ++k) {
            u64 w2 = dup2(W1[k * HID + j]);
            ulonglong2 x01 = *(const ulonglong2*)&xsp[k][pb];
            ulonglong2 x23 = *(const ulonglong2*)&xsp[k][pb + 2];
            acc[0] = ffma2_(x01.x, w2, acc[0]);
            acc[1] = ffma2_(x01.y, w2, acc[1]);
            acc[2] = ffma2_(x23.x, w2, acc[2]);
            acc[3] = ffma2_(x23.y, w2, acc[3]);
        }
        #pragma unroll
        for (int p = 0; p < 4; ++p) hT[j][pb + p] = relu2_(acc[p]);
    }
    __syncthreads();

    // Layer 2
    mlp128(W2, j, pb, hT, acc);
    {
        u64 b2d = dup2(b2[j]);
        __syncthreads();             // all hT reads done before overwrite
        #pragma unroll
        for (int p = 0; p < 4; ++p)
            hT[j][pb + p] = relu2_(fadd2_(acc[p], b2d));
    }
    __syncthreads();

    // Score projection
    mlp128(Ws, j, pb, hT, acc);
    u64 bsd = agent ? dup2(bs1[j]) : 0ull;
    #pragma unroll
    for (int p = 0; p < 4; ++p) {
        u64 v = agent ? fadd2_(acc[p], bsd) : acc[p];
        float2 f = unpack2(v);
        int row = rbase + 2 * (pb + p);
        outp[row * HID + j]       = f.x;
        outp[(row + 1) * HID + j] = f.y;
    }
}

// ---------------------------------------------------------------------------
// Kernel 2: pairwise scores, f32x2 packed over (h, h+1) — natural layout,
// no transpose, no duplication. Tile 64a x 32r, 128 threads, 4x4 per thread
// (a = ty+16i, r = tx+8jj for conflict-free strided smem reads, pitch 68).
// h in 2 chunks of 64; accumulators packed over h-lanes, horizontal add once.
// ---------------------------------------------------------------------------
__global__ __launch_bounds__(128, 4) void pair_kernel(
    const float* __restrict__ Ws2, const float* __restrict__ bs2,
    float* __restrict__ out)
{
    __shared__ __align__(16) float As[64 * 68];   // [a][h_local], pitch 68
    __shared__ __align__(16) float Rs[32 * 68];   // [r][h_local]
    __shared__ __align__(16) u64   wsp[64];       // Ws2 as natural h-pairs

    int t  = threadIdx.x;
    int tx = t & 7;          // r = tx + 8*jj
    int ty = t >> 3;         // a = ty + 16*i
    int a0 = blockIdx.y * 64;
    int r0 = blockIdx.x * 32;

    if (t < 64) wsp[t] = ((const u64*)Ws2)[t];

    u64 acc[4][4];
    #pragma unroll
    for (int i = 0; i < 4; ++i)
        #pragma unroll
        for (int jj = 0; jj < 4; ++jj) acc[i][jj] = 0ull;

    for (int c = 0; c < 2; ++c) {
        int hb = 64 * c;
        __syncthreads();   // previous chunk's reads done (and wsp on c==0)

        #pragma unroll
        for (int it = 0; it < 8; ++it) {
            int idx = t + 128 * it;
            int row = idx >> 4, c4 = idx & 15;
            *(float4*)&As[row * 68 + 4 * c4] =
                *(const float4*)&g_PA[(size_t)(a0 + row) * HID + hb + 4 * c4];
        }
        #pragma unroll
        for (int it = 0; it < 4; ++it) {
            int idx = t + 128 * it;
            int row = idx >> 4, c4 = idx & 15;
            *(float4*)&Rs[row * 68 + 4 * c4] =
                *(const float4*)&g_PR[(size_t)(r0 + row) * HID + hb + 4 * c4];
        }
        __syncthreads();

        #pragma unroll 2
        for (int h4 = 0; h4 < 16; ++h4) {   // 4 h per iter (2 packed pairs)
            ulonglong2 wv = *(const ulonglong2*)&wsp[32 * c + 2 * h4];
            ulonglong2 av[4], rv[4];
            #pragma unroll
            for (int i = 0; i < 4; ++i)
                av[i] = *(const ulonglong2*)&As[(ty + 16 * i) * 68 + 4 * h4];
            #pragma unroll
            for (int jj = 0; jj < 4; ++jj)
                rv[jj] = *(const ulonglong2*)&Rs[(tx + 8 * jj) * 68 + 4 * h4];
            #pragma unroll
            for (int i = 0; i < 4; ++i)
                #pragma unroll
                for (int jj = 0; jj < 4; ++jj) {
                    acc[i][jj] = addrelufma(acc[i][jj], av[i].x, rv[jj].x, wv.x);
                    acc[i][jj] = addrelufma(acc[i][jj], av[i].y, rv[jj].y, wv.y);
                }
        }
    }

    float b = *bs2;
    #pragma unroll
    for (int i = 0; i < 4; ++i) {
        int a = a0 + ty + 16 * i;
        #pragma unroll
        for (int jj = 0; jj < 4; ++jj) {
            float2 p = unpack2(acc[i][jj]);
            out[(size_t)a * NR + r0 + tx + 8 * jj] = (p.x + p.y) + b;
        }
    }
}

// ---------------------------------------------------------------------------
extern "C" void kernel_launch(void* const* d_in, const int* in_sizes, int n_in,
                              void* d_out, int out_size)
{
    const float* xa  = (const float*)d_in[0];
    const float* xr  = (const float*)d_in[1];
    const float* Wa1 = (const float*)d_in[2];
    const float* ba1 = (const float*)d_in[3];
    const float* Wa2 = (const float*)d_in[4];
    const float* ba2 = (const float*)d_in[5];
    const float* Wr1 = (const float*)d_in[6];
    const float* br1 = (const float*)d_in[7];
    const float* Wr2 = (const float*)d_in[8];
    const float* br2 = (const float*)d_in[9];
    const float* Ws1 = (const float*)d_in[10];
    const float* bs1 = (const float*)d_in[11];
    const float* Ws2 = (const float*)d_in[12];
    const float* bs2 = (const float*)d_in[13];
    float* out = (float*)d_out;

    embed_kernel<<<128, 256>>>(xa, xr, Wa1, ba1, Wa2, ba2,
                               Wr1, br1, Wr2, br2, Ws1, bs1);
    pair_kernel<<<dim3(NR / 32, NA / 64), 128>>>(Ws2, bs2, out);
}

// round 4
// speedup vs baseline: 1.4918x; 1.0527x over previous
#include <cuda_runtime.h>

typedef unsigned long long u64;

#define HID 128
#define NA  1024
#define NR  1024

// Scratch: PA (bs1 folded in) and PR, row-major [row][h]
__device__ float g_PA[NA * HID];
__device__ float g_PR[NR * HID];

// ---------------- packed f32x2 helpers (sm_103a FADD2/FFMA2) ----------------
__device__ __forceinline__ u64 dup2(float v) {
    u64 d; asm("mov.b64 %0,{%1,%1};" : "=l"(d) : "f"(v)); return d;
}
__device__ __forceinline__ u64 pack2(float lo, float hi) {
    u64 d; asm("mov.b64 %0,{%1,%2};" : "=l"(d) : "f"(lo), "f"(hi)); return d;
}
__device__ __forceinline__ float2 unpack2(u64 d) {
    float2 r; asm("mov.b64 {%0,%1},%2;" : "=f"(r.x), "=f"(r.y) : "l"(d)); return r;
}
__device__ __forceinline__ u64 fadd2_(u64 a, u64 b) {
    u64 d; asm("add.rn.f32x2 %0,%1,%2;" : "=l"(d) : "l"(a), "l"(b)); return d;
}
__device__ __forceinline__ u64 ffma2_(u64 a, u64 b, u64 c) {
    u64 d; asm("fma.rn.f32x2 %0,%1,%2,%3;" : "=l"(d) : "l"(a), "l"(b), "l"(c)); return d;
}
__device__ __forceinline__ u64 relu2_(u64 x) {
    u64 d;
    asm("{\n\t.reg .f32 lo,hi;\n\t"
        "mov.b64 {lo,hi},%1;\n\t"
        "max.f32 lo,lo,0f00000000;\n\t"
        "max.f32 hi,hi,0f00000000;\n\t"
        "mov.b64 %0,{lo,hi};\n\t}"
        : "=l"(d) : "l"(x));
    return d;
}
// acc += relu(a2 + r2) * w2   (2 h-lanes packed)
__device__ __forceinline__ u64 addrelufma(u64 acc, u64 a2, u64 r2, u64 w2) {
    asm("{\n\t.reg .b64 t;\n\t.reg .f32 lo,hi;\n\t"
        "add.rn.f32x2 t,%1,%2;\n\t"
        "mov.b64 {lo,hi},t;\n\t"
        "max.f32 lo,lo,0f00000000;\n\t"
        "max.f32 hi,hi,0f00000000;\n\t"
        "mov.b64 t,{lo,hi};\n\t"
        "fma.rn.f32x2 %0,t,%3,%0;\n\t}"
        : "+l"(acc) : "l"(a2), "l"(r2), "l"(w2));
    return acc;
}

// ---------------------------------------------------------------------------
// 128x128 MLP layer pass, f32x2 row-pairs, 8-deep register prefetch of the
// weight column. hT is [k][row-pair] (broadcast reads, conflict-free).
// ---------------------------------------------------------------------------
__device__ __forceinline__ void mlp128(const float* __restrict__ Wp, int j, int pb,
                                       const u64 (*__restrict__ hT)[8], u64 acc[4])
{
    acc[0] = acc[1] = acc[2] = acc[3] = 0ull;
    float wA[8], wB[8];
    #pragma unroll
    for (int i = 0; i < 8; ++i) wA[i] = Wp[i * HID + j];
    #pragma unroll 1
    for (int kb = 0; kb < 128; kb += 16) {
        #pragma unroll
        for (int i = 0; i < 8; ++i) wB[i] = Wp[(kb + 8 + i) * HID + j];
        #pragma unroll
        for (int i = 0; i < 8; ++i) {
            int k = kb + i;
            u64 w2 = dup2(wA[i]);
            ulonglong2 x01 = *(const ulonglong2*)&hT[k][pb];
            ulonglong2 x23 = *(const ulonglong2*)&hT[k][pb + 2];
            acc[0] = ffma2_(x01.x, w2, acc[0]);
            acc[1] = ffma2_(x01.y, w2, acc[1]);
            acc[2] = ffma2_(x23.x, w2, acc[2]);
            acc[3] = ffma2_(x23.y, w2, acc[3]);
        }
        #pragma unroll
        for (int i = 0; i < 8; ++i)
            wA[i] = (kb + 16 + i < 128) ? Wp[(kb + 16 + i) * HID + j] : 0.f;
        #pragma unroll
        for (int i = 0; i < 8; ++i) {
            int k = kb + 8 + i;
            u64 w2 = dup2(wB[i]);
            ulonglong2 x01 = *(const ulonglong2*)&hT[k][pb];
            ulonglong2 x23 = *(const ulonglong2*)&hT[k][pb + 2];
            acc[0] = ffma2_(x01.x, w2, acc[0]);
            acc[1] = ffma2_(x01.y, w2, acc[1]);
            acc[2] = ffma2_(x23.x, w2, acc[2]);
            acc[3] = ffma2_(x23.y, w2, acc[3]);
        }
    }
}

// ---------------------------------------------------------------------------
// Kernel 1: fused MLP chain. 128 blocks (64 agent + 64 region) x 256 threads,
// 16 rows per block. j = t&127 (column), half = t>>7 picks 4 of 8 row-pairs.
// ---------------------------------------------------------------------------
__global__ __launch_bounds__(256) void embed_kernel(
    const float* __restrict__ xa,  const float* __restrict__ xr,
    const float* __restrict__ Wa1, const float* __restrict__ ba1,
    const float* __restrict__ Wa2, const float* __restrict__ ba2,
    const float* __restrict__ Wr1, const float* __restrict__ br1,
    const float* __restrict__ Wr2, const float* __restrict__ br2,
    const float* __restrict__ Ws1, const float* __restrict__ bs1)
{
    const int ROWS = 16;
    int blk = blockIdx.x;
    bool agent = blk < 64;
    int rbase = (agent ? blk : blk - 64) * ROWS;
    int idim = agent ? 24 : 20;
    const float* x  = agent ? (xa + rbase * 24) : (xr + rbase * 20);
    const float* W1 = agent ? Wa1 : Wr1;
    const float* b1 = agent ? ba1 : br1;
    const float* W2 = agent ? Wa2 : Wr2;
    const float* b2 = agent ? ba2 : br2;
    const float* Ws = agent ? Ws1 : (Ws1 + HID * HID);
    float* outp = agent ? g_PA : g_PR;

    __shared__ __align__(16) u64 xsp[24][8];   // packed input [k][row-pair]
    __shared__ __align__(16) u64 hT[HID][8];   // packed activ [k][row-pair]

    int t = threadIdx.x;
    int j = t & 127;
    int pb = (t >> 7) * 4;     // row-pair base (0 or 4)

    // Stage packed input rows
    for (int i = t; i < idim * 8; i += 256) {
        int k = i >> 3, p = i & 7;
        xsp[k][p] = pack2(x[(2 * p) * idim + k], x[(2 * p + 1) * idim + k]);
    }
    __syncthreads();

    // Layer 1
    u64 acc[4];
    {
        u64 bp = dup2(b1[j]);
        acc[0] = acc[1] = acc[2] = acc[3] = bp;
        #pragma unroll 4
        for (int k = 0; k < idim; ++k) {
            u64 w2 = dup2(W1[k * HID + j]);
            ulonglong2 x01 = *(const ulonglong2*)&xsp[k][pb];
            ulonglong2 x23 = *(const ulonglong2*)&xsp[k][pb + 2];
            acc[0] = ffma2_(x01.x, w2, acc[0]);
            acc[1] = ffma2_(x01.y, w2, acc[1]);
            acc[2] = ffma2_(x23.x, w2, acc[2]);
            acc[3] = ffma2_(x23.y, w2, acc[3]);
        }
        #pragma unroll
        for (int p = 0; p < 4; ++p) hT[j][pb + p] = relu2_(acc[p]);
    }
    __syncthreads();

    // Layer 2
    mlp128(W2, j, pb, hT, acc);
    {
        u64 b2d = dup2(b2[j]);
        __syncthreads();             // all hT reads done before overwrite
        #pragma unroll
        for (int p = 0; p < 4; ++p)
            hT[j][pb + p] = relu2_(fadd2_(acc[p], b2d));
    }
    __syncthreads();

    // Score projection
    mlp128(Ws, j, pb, hT, acc);
    u64 bsd = agent ? dup2(bs1[j]) : 0ull;
    #pragma unroll
    for (int p = 0; p < 4; ++p) {
        u64 v = agent ? fadd2_(acc[p], bsd) : acc[p];
        float2 f = unpack2(v);
        int row = rbase + 2 * (pb + p);
        outp[row * HID + j]       = f.x;
        outp[(row + 1) * HID + j] = f.y;
    }
}

// ---------------------------------------------------------------------------
// Kernel 2: pairwise scores, f32x2 packed over (h, h+1) — natural layout,
// no transpose, no duplication. Tile 64a x 32r, 128 threads, 4x4 per thread
// (a = ty+16i, r = tx+8jj for conflict-free strided smem reads, pitch 68).
// h in 2 chunks of 64; accumulators packed over h-lanes, horizontal add once.
// ---------------------------------------------------------------------------
__global__ __launch_bounds__(128, 4) void pair_kernel(
    const float* __restrict__ Ws2, const float* __restrict__ bs2,
    float* __restrict__ out)
{
    __shared__ __align__(16) float As[64 * 68];   // [a][h_local], pitch 68
    __shared__ __align__(16) float Rs[32 * 68];   // [r][h_local]
    __shared__ __align__(16) u64   wsp[64];       // Ws2 as natural h-pairs

    int t  = threadIdx.x;
    int tx = t & 7;          // r = tx + 8*jj
    int ty = t >> 3;         // a = ty + 16*i
    int a0 = blockIdx.y * 64;
    int r0 = blockIdx.x * 32;

    if (t < 64) wsp[t] = ((const u64*)Ws2)[t];

    u64 acc[4][4];
    #pragma unroll
    for (int i = 0; i < 4; ++i)
        #pragma unroll
        for (int jj = 0; jj < 4; ++jj) acc[i][jj] = 0ull;

    for (int c = 0; c < 2; ++c) {
        int hb = 64 * c;
        __syncthreads();   // previous chunk's reads done (and wsp on c==0)

        #pragma unroll
        for (int it = 0; it < 8; ++it) {
            int idx = t + 128 * it;
            int row = idx >> 4, c4 = idx & 15;
            *(float4*)&As[row * 68 + 4 * c4] =
                *(const float4*)&g_PA[(size_t)(a0 + row) * HID + hb + 4 * c4];
        }
        #pragma unroll
        for (int it = 0; it < 4; ++it) {
            int idx = t + 128 * it;
            int row = idx >> 4, c4 = idx & 15;
            *(float4*)&Rs[row * 68 + 4 * c4] =
                *(const float4*)&g_PR[(size_t)(r0 + row) * HID + hb + 4 * c4];
        }
        __syncthreads();

        #pragma unroll 2
        for (int h4 = 0; h4 < 16; ++h4) {   // 4 h per iter (2 packed pairs)
            ulonglong2 wv = *(const ulonglong2*)&wsp[32 * c + 2 * h4];
            ulonglong2 av[4], rv[4];
            #pragma unroll
            for (int i = 0; i < 4; ++i)
                av[i] = *(const ulonglong2*)&As[(ty + 16 * i) * 68 + 4 * h4];
            #pragma unroll
            for (int jj = 0; jj < 4; ++jj)
                rv[jj] = *(const ulonglong2*)&Rs[(tx + 8 * jj) * 68 + 4 * h4];
            #pragma unroll
            for (int i = 0; i < 4; ++i)
                #pragma unroll
                for (int jj = 0; jj < 4; ++jj) {
                    acc[i][jj] = addrelufma(acc[i][jj], av[i].x, rv[jj].x, wv.x);
                    acc[i][jj] = addrelufma(acc[i][jj], av[i].y, rv[jj].y, wv.y);
                }
        }
    }

    float b = *bs2;
    #pragma unroll
    for (int i = 0; i < 4; ++i) {
        int a = a0 + ty + 16 * i;
        #pragma unroll
        for (int jj = 0; jj < 4; ++jj) {
            float2 p = unpack2(acc[i][jj]);
            out[(size_t)a * NR + r0 + tx + 8 * jj] = (p.x + p.y) + b;
        }
    }
}

// ---------------------------------------------------------------------------
extern "C" void kernel_launch(void* const* d_in, const int* in_sizes, int n_in,
                              void* d_out, int out_size)
{
    const float* xa  = (const float*)d_in[0];
    const float* xr  = (const float*)d_in[1];
    const float* Wa1 = (const float*)d_in[2];
    const float* ba1 = (const float*)d_in[3];
    const float* Wa2 = (const float*)d_in[4];
    const float* ba2 = (const float*)d_in[5];
    const float* Wr1 = (const float*)d_in[6];
    const float* br1 = (const float*)d_in[7];
    const float* Wr2 = (const float*)d_in[8];
    const float* br2 = (const float*)d_in[9];
    const float* Ws1 = (const float*)d_in[10];
    const float* bs1 = (const float*)d_in[11];
    const float* Ws2 = (const float*)d_in[12];
    const float* bs2 = (const float*)d_in[13];
    float* out = (float*)d_out;

    embed_kernel<<<128, 256>>>(xa, xr, Wa1, ba1, Wa2, ba2,
                               Wr1, br1, Wr2, br2, Ws1, bs1);
    pair_kernel<<<dim3(NR / 32, NA / 64), 128>>>(Ws2, bs2, out);
}